// round 16
// baseline (speedup 1.0000x reference)
#include <cuda_runtime.h>
#include <cstdint>
#include <math.h>

// ---------------- problem constants ----------------
constexpr int Bq = 2, Sq = 1024, Dq = 2048, Hq = 16, Dhq = 128, Fq = 5504, Rq = 8, Lq = 2;
constexpr int Mq = Bq * Sq;  // 2048 tokens

constexpr size_t DD  = (size_t)Dq * Dq;
constexpr size_t FD  = (size_t)Fq * Dq;
constexpr size_t MD  = (size_t)Mq * Dq;
constexpr size_t MF  = (size_t)Mq * Fq;
constexpr size_t SCN = (size_t)Bq * Hq * Sq * Sq;

constexpr size_t OFF_WQKV = 0;                                   // [L][3D][D]
constexpr size_t OFF_WO = OFF_WQKV + (size_t)Lq * 3 * DD;
constexpr size_t OFF_WG = OFF_WO + (size_t)Lq * DD;
constexpr size_t OFF_WU = OFF_WG + (size_t)Lq * FD;
constexpr size_t OFF_WD = OFF_WU + (size_t)Lq * FD;
constexpr size_t OFF_X  = OFF_WD + (size_t)Lq * FD;
constexpr size_t OFF_H  = OFF_X + MD;
constexpr size_t OFF_Q  = OFF_H + MD;
constexpr size_t OFF_K  = OFF_Q + MD;     // contiguous with Q
constexpr size_t OFF_V  = OFF_K + MD;     // contiguous with K
constexpr size_t OFF_C  = OFF_V + MD;
constexpr size_t OFF_S  = OFF_C + MD;
constexpr size_t OFF_G  = OFF_S + SCN;
constexpr size_t OFF_U  = OFF_G + MF;
constexpr size_t OFF_T  = OFF_U + MF;
constexpr size_t OFF_RT = OFF_T + (size_t)Mq * Rq * 4;           // rope tables
constexpr size_t SCRATCH_TOTAL = OFF_RT + (size_t)2 * Sq * 64;

__device__ float g_scratch[SCRATCH_TOTAL];

// ---------------- NF4 tables ----------------
__device__ __constant__ float NF4C[16] = {
    -1.0f, -0.6961928009986877f, -0.5250730514526367f, -0.39491748809814453f,
    -0.28444138169288635f, -0.18477343022823334f, -0.09105003625154495f, 0.0f,
    0.07958029955625534f, 0.16093020141124725f, 0.24611230194568634f,
    0.33791524171829224f, 0.44070982933044434f, 0.5626170039176941f,
    0.7229568362236023f, 1.0f};

__device__ __constant__ float NF4M[15] = {
    (-1.0f + -0.6961928009986877f) * 0.5f,
    (-0.6961928009986877f + -0.5250730514526367f) * 0.5f,
    (-0.5250730514526367f + -0.39491748809814453f) * 0.5f,
    (-0.39491748809814453f + -0.28444138169288635f) * 0.5f,
    (-0.28444138169288635f + -0.18477343022823334f) * 0.5f,
    (-0.18477343022823334f + -0.09105003625154495f) * 0.5f,
    (-0.09105003625154495f + 0.0f) * 0.5f,
    (0.0f + 0.07958029955625534f) * 0.5f,
    (0.07958029955625534f + 0.16093020141124725f) * 0.5f,
    (0.16093020141124725f + 0.24611230194568634f) * 0.5f,
    (0.24611230194568634f + 0.33791524171829224f) * 0.5f,
    (0.33791524171829224f + 0.44070982933044434f) * 0.5f,
    (0.44070982933044434f + 0.5626170039176941f) * 0.5f,
    (0.5626170039176941f + 0.7229568362236023f) * 0.5f,
    (0.7229568362236023f + 1.0f) * 0.5f};

__device__ __forceinline__ uint32_t tf32r(float x) {
    uint32_t r;
    asm("cvt.rna.tf32.f32 %0, %1;" : "=r"(r) : "f"(x));
    return r;
}
__device__ __forceinline__ float tf32rf(float x) {
    return __uint_as_float(tf32r(x));
}

// ---------------- dequant: one warp per FOUR 64-blocks, 2 float4/thread ----------------
__global__ void k_dequant(const float* __restrict__ w, float* __restrict__ o, int nblk) {
    int warp = blockIdx.x * (blockDim.x >> 5) + (threadIdx.x >> 5);
    int lane = threadIdx.x & 31;
    int blk = warp * 4 + (lane >> 3);
    if (blk >= nblk) return;
    int sub = lane & 7;
    const float4* p = (const float4*)(w + (size_t)blk * 64);
    float4 v0 = p[sub], v1 = p[sub + 8];
    float am = fmaxf(fmaxf(fabsf(v0.x), fabsf(v0.y)), fmaxf(fabsf(v0.z), fabsf(v0.w)));
    am = fmaxf(am, fmaxf(fmaxf(fabsf(v1.x), fabsf(v1.y)), fmaxf(fabsf(v1.z), fabsf(v1.w))));
#pragma unroll
    for (int s = 4; s; s >>= 1) am = fmaxf(am, __shfl_xor_sync(0xffffffffu, am, s));
    float d = fmaxf(am, 1e-12f);
    float t[15];
#pragma unroll
    for (int i = 0; i < 15; i++) t[i] = NF4M[i] * d;
    auto code = [&](float v) -> float {
        int idx = 0;
#pragma unroll
        for (int i = 0; i < 15; i++) idx += (v > t[i]) ? 1 : 0;
        return tf32rf(NF4C[idx] * am);
    };
    float4 q0, q1;
    q0.x = code(v0.x); q0.y = code(v0.y); q0.z = code(v0.z); q0.w = code(v0.w);
    q1.x = code(v1.x); q1.y = code(v1.y); q1.z = code(v1.z); q1.w = code(v1.w);
    float4* op = (float4*)(o + (size_t)blk * 64);
    op[sub] = q0; op[sub + 8] = q1;
}

// ---------------- block reductions (blockDim = 256) ----------------
__device__ __forceinline__ float blk_sum(float v) {
    __shared__ float sh_s[8];
#pragma unroll
    for (int s = 16; s; s >>= 1) v += __shfl_xor_sync(0xffffffffu, v, s);
    if ((threadIdx.x & 31) == 0) sh_s[threadIdx.x >> 5] = v;
    __syncthreads();
    if (threadIdx.x < 32) {
        v = (threadIdx.x < 8) ? sh_s[threadIdx.x] : 0.0f;
#pragma unroll
        for (int s = 4; s; s >>= 1) v += __shfl_xor_sync(0xffffffffu, v, s);
        if (threadIdx.x == 0) sh_s[0] = v;
    }
    __syncthreads();
    float r = sh_s[0];
    __syncthreads();
    return r;
}

__device__ __forceinline__ float blk_max(float v) {
    __shared__ float sh_m[8];
#pragma unroll
    for (int s = 16; s; s >>= 1) v = fmaxf(v, __shfl_xor_sync(0xffffffffu, v, s));
    if ((threadIdx.x & 31) == 0) sh_m[threadIdx.x >> 5] = v;
    __syncthreads();
    if (threadIdx.x < 32) {
        v = (threadIdx.x < 8) ? sh_m[threadIdx.x] : -3.4e38f;
#pragma unroll
        for (int s = 4; s; s >>= 1) v = fmaxf(v, __shfl_xor_sync(0xffffffffu, v, s));
        if (threadIdx.x == 0) sh_m[0] = v;
    }
    __syncthreads();
    float r = sh_m[0];
    __syncthreads();
    return r;
}

// ---------------- plain rmsnorm (rnd: write tf32-rounded for GEMM A-side) ----------------
__global__ void k_rmsnorm(const float* __restrict__ x, const float* __restrict__ w,
                          float* __restrict__ o, int rnd) {
    int row = blockIdx.x;
    const float* p = x + (size_t)row * Dq;
    float s = 0.0f;
#pragma unroll
    for (int i = threadIdx.x; i < Dq; i += 256) { float v = p[i]; s += v * v; }
    s = blk_sum(s);
    float mean = s * (1.0f / (float)Dq);
    float r = (float)(1.0 / sqrt((double)mean + 1e-5));
#pragma unroll
    for (int i = threadIdx.x; i < Dq; i += 256) {
        float hv = (p[i] * r) * w[i];
        o[(size_t)row * Dq + i] = rnd ? tf32rf(hv) : hv;
    }
}

// ---------------- fused rmsnorm + 3x lora-t (qkv); h written tf32-rounded ----------------
__global__ void k_rmsnorm_lora(
    const float* __restrict__ x, const float* __restrict__ w,
    const float* __restrict__ A0, const float* __restrict__ A1, const float* __restrict__ A2,
    float* __restrict__ h, float* __restrict__ t0, float* __restrict__ t1,
    float* __restrict__ t2) {
    __shared__ float sx[Dq];
    __shared__ float sh2[8][Rq];
    int row = blockIdx.x, tid = threadIdx.x;
    const float* p = x + (size_t)row * Dq;
    float s = 0.0f;
#pragma unroll
    for (int i = tid; i < Dq; i += 256) { float v = p[i]; sx[i] = v; s += v * v; }
    s = blk_sum(s);
    float mean = s * (1.0f / (float)Dq);
    float r = (float)(1.0 / sqrt((double)mean + 1e-5));
#pragma unroll
    for (int i = tid; i < Dq; i += 256) {
        float hv = (sx[i] * r) * w[i];
        sx[i] = hv;                                   // full precision for lora
        h[(size_t)row * Dq + i] = tf32rf(hv);         // rounded for GEMM A-side
    }
    __syncthreads();
    const float* As[3] = {A0, A1, A2};
    float* ts[3] = {t0, t1, t2};
#pragma unroll
    for (int mt = 0; mt < 3; mt++) {
        const float* A = As[mt];
        float acc[Rq] = {};
        for (int k = tid; k < Dq; k += 256) {
            float xv = sx[k];
#pragma unroll
            for (int rr = 0; rr < Rq; rr++) acc[rr] += xv * A[(size_t)rr * Dq + k];
        }
#pragma unroll
        for (int rr = 0; rr < Rq; rr++) {
            float v = acc[rr];
#pragma unroll
            for (int s2 = 16; s2; s2 >>= 1) v += __shfl_xor_sync(0xffffffffu, v, s2);
            if ((tid & 31) == 0) sh2[tid >> 5][rr] = v;
        }
        __syncthreads();
        if (tid < Rq) {
            float v = 0.0f;
#pragma unroll
            for (int w2 = 0; w2 < 8; w2++) v += sh2[w2][tid];
            ts[mt][(size_t)row * Rq + tid] = v;
        }
        __syncthreads();
    }
}

// ---------------- lora t = x @ A^T (o-proj) ----------------
__global__ void k_lora_t(const float* __restrict__ x, const float* __restrict__ A,
                         float* __restrict__ t) {
    int m = blockIdx.x;
    const float* xr = x + (size_t)m * Dq;
    float acc[Rq] = {};
    for (int k = threadIdx.x; k < Dq; k += 256) {
        float xv = xr[k];
#pragma unroll
        for (int r = 0; r < Rq; r++) acc[r] += xv * A[(size_t)r * Dq + k];
    }
    __shared__ float sh[8][Rq];
#pragma unroll
    for (int r = 0; r < Rq; r++) {
        float v = acc[r];
#pragma unroll
        for (int s = 16; s; s >>= 1) v += __shfl_xor_sync(0xffffffffu, v, s);
        if ((threadIdx.x & 31) == 0) sh[threadIdx.x >> 5][r] = v;
    }
    __syncthreads();
    if (threadIdx.x < Rq) {
        float v = 0.0f;
#pragma unroll
        for (int w2 = 0; w2 < 8; w2++) v += sh[w2][threadIdx.x];
        t[(size_t)m * Rq + threadIdx.x] = v;
    }
}

// ================= tf32 mma helpers =================
__device__ __forceinline__ uint32_t smem_u32(const void* p) {
    uint32_t a;
    asm("{ .reg .u64 t; cvta.to.shared.u64 t, %1; cvt.u32.u64 %0, t; }" : "=r"(a) : "l"(p));
    return a;
}
__device__ __forceinline__ void mma_tf32(float* c, const uint32_t* a, const uint32_t* b) {
    asm volatile(
        "mma.sync.aligned.m16n8k8.row.col.f32.tf32.tf32.f32 "
        "{%0,%1,%2,%3},{%4,%5,%6,%7},{%8,%9},{%0,%1,%2,%3};"
        : "+f"(c[0]), "+f"(c[1]), "+f"(c[2]), "+f"(c[3])
        : "r"(a[0]), "r"(a[1]), "r"(a[2]), "r"(a[3]), "r"(b[0]), "r"(b[1]));
}
__device__ __forceinline__ void cp_async16(uint32_t dst, const float* src) {
    asm volatile("cp.async.cg.shared.global [%0], [%1], 16;"
                 :: "r"(dst), "l"(__cvta_generic_to_global(src)));
}

// ---------------- main linear GEMM (two-stage + fused-QKV mode) ----------------
constexpr int MMA_SMEM_BYTES = 2 * 2 * 128 * 36 * 4;  // 73728

__global__ void __launch_bounds__(256, 2) k_gemm_mma(
    const float* __restrict__ A, const float* __restrict__ W,
    const float* TL, const float* BL0, const float* BL1, const float* BL2,
    const float* __restrict__ gate,
    float* out, int N2, int K2, int lora, int resid, int rnd, int qkv) {
    extern __shared__ float sm[];
    uint32_t sb = smem_u32(sm);
    int tid = threadIdx.x, lane = tid & 31, wid = tid >> 5;
    int wm = wid & 1, wn = wid >> 1;
    int m0 = blockIdx.y * 128, n0 = blockIdx.x * 128;
    const float* Ap = A + (size_t)m0 * K2;
    const float* Wp = W + (size_t)n0 * K2;

    const float* BL = BL0;
    int nloc0 = n0;
    if (qkv) {
        int seg = blockIdx.x >> 4;
        nloc0 = n0 - seg * 2048;
        TL += (size_t)seg * Mq * Rq;
        BL = (seg == 0) ? BL0 : ((seg == 1) ? BL1 : BL2);
        rnd = (seg == 2) ? 1 : 0;             // only V pre-rounds
        out += (size_t)seg * MD;
    }

    auto issue_chunk = [&](int kt, int buf) {
        uint32_t base = sb + (uint32_t)buf * 36864u;
#pragma unroll
        for (int i = 0; i < 4; i++) {
            int fi = tid + i * 256;
            int row = fi >> 3, q = fi & 7;
            cp_async16(base + (uint32_t)((row * 36 + q * 4) * 4),
                       Ap + (size_t)row * K2 + kt + q * 4);
        }
#pragma unroll
        for (int i = 0; i < 4; i++) {
            int fi = tid + i * 256;
            int row = fi >> 3, q = fi & 7;
            cp_async16(base + 18432u + (uint32_t)((row * 36 + q * 4) * 4),
                       Wp + (size_t)row * K2 + kt + q * 4);
        }
        asm volatile("cp.async.commit_group;");
    };

    float acc[4][4][4] = {};
    int abase = (wm * 64 + (lane >> 2)) * 36 + (lane & 3);
    int bbase = (wn * 32 + (lane >> 2)) * 36 + (lane & 3);

    int nch = K2 >> 5;
    issue_chunk(0, 0);
    for (int c = 0; c < nch; c++) {
        if (c + 1 < nch) {
            issue_chunk((c + 1) << 5, (c + 1) & 1);
            asm volatile("cp.async.wait_group 1;");
        } else {
            asm volatile("cp.async.wait_group 0;");
        }
        __syncthreads();
        const float* sA = sm + (c & 1) * 9216;
        const float* sB = sA + 4608;
#pragma unroll
        for (int ks = 0; ks < 4; ks++) {
            uint32_t af[4][4], bf[4][2];
#pragma unroll
            for (int mf = 0; mf < 4; mf++) {
                const float* p = sA + abase + mf * 576 + ks * 8;
                af[mf][0] = __float_as_uint(p[0]);
                af[mf][1] = __float_as_uint(p[288]);
                af[mf][2] = __float_as_uint(p[4]);
                af[mf][3] = __float_as_uint(p[292]);
            }
#pragma unroll
            for (int nf = 0; nf < 4; nf++) {
                const float* p = sB + bbase + nf * 288 + ks * 8;
                bf[nf][0] = __float_as_uint(p[0]);
                bf[nf][1] = __float_as_uint(p[4]);
            }
#pragma unroll
            for (int mf = 0; mf < 4; mf++)
#pragma unroll
                for (int nf = 0; nf < 4; nf++) mma_tf32(acc[mf][nf], af[mf], bf[nf]);
        }
        __syncthreads();
    }

#pragma unroll
    for (int nf = 0; nf < 4; nf++) {
        int n = nloc0 + wn * 32 + nf * 8 + (lane & 3) * 2;
        float bl0[8], bl1[8];
        if (lora) {
            *(float4*)bl0       = *(const float4*)(BL + (size_t)n * 8);
            *(float4*)(bl0 + 4) = *(const float4*)(BL + (size_t)n * 8 + 4);
            *(float4*)bl1       = *(const float4*)(BL + (size_t)(n + 1) * 8);
            *(float4*)(bl1 + 4) = *(const float4*)(BL + (size_t)(n + 1) * 8 + 4);
        }
#pragma unroll
        for (int mf = 0; mf < 4; mf++) {
            int m = m0 + wm * 64 + mf * 16 + (lane >> 2);
            float* c = acc[mf][nf];
            float c0 = c[0], c1 = c[1], c2 = c[2], c3 = c[3];
            if (lora) {
                float tl[8];
                *(float4*)tl       = *(const float4*)(TL + (size_t)m * 8);
                *(float4*)(tl + 4) = *(const float4*)(TL + (size_t)m * 8 + 4);
                float d0 = 0.0f, d1 = 0.0f;
#pragma unroll
                for (int r = 0; r < 8; r++) { d0 += tl[r] * bl0[r]; d1 += tl[r] * bl1[r]; }
                c0 += 2.0f * d0; c1 += 2.0f * d1;
                float tl2[8];
                *(float4*)tl2       = *(const float4*)(TL + (size_t)(m + 8) * 8);
                *(float4*)(tl2 + 4) = *(const float4*)(TL + (size_t)(m + 8) * 8 + 4);
                float e0 = 0.0f, e1 = 0.0f;
#pragma unroll
                for (int r = 0; r < 8; r++) { e0 += tl2[r] * bl0[r]; e1 += tl2[r] * bl1[r]; }
                c2 += 2.0f * e0; c3 += 2.0f * e1;
            }
            if (gate) {   // fused silu(gate) * up  (fast exp: rel err ~5e-7, << tf32 noise)
                float2 g0 = *(const float2*)(gate + (size_t)m * N2 + n);
                float2 g1 = *(const float2*)(gate + (size_t)(m + 8) * N2 + n);
                float s0 = __fdiv_rn(1.0f, 1.0f + __expf(-g0.x));
                float s1 = __fdiv_rn(1.0f, 1.0f + __expf(-g0.y));
                float s2 = __fdiv_rn(1.0f, 1.0f + __expf(-g1.x));
                float s3 = __fdiv_rn(1.0f, 1.0f + __expf(-g1.y));
                c0 = (g0.x * s0) * c0; c1 = (g0.y * s1) * c1;
                c2 = (g1.x * s2) * c2; c3 = (g1.y * s3) * c3;
            }
            float* o0 = out + (size_t)m * N2 + n;
            float* o1 = out + (size_t)(m + 8) * N2 + n;
            if (resid) {
                float2 r0 = *(const float2*)o0;
                float2 r1 = *(const float2*)o1;
                c0 += r0.x; c1 += r0.y; c2 += r1.x; c3 += r1.y;
            }
            if (rnd) {
                c0 = tf32rf(c0); c1 = tf32rf(c1); c2 = tf32rf(c2); c3 = tf32rf(c3);
            }
            *(float2*)o0 = make_float2(c0, c1);
            *(float2*)o1 = make_float2(c2, c3);
        }
    }
}

// ---------------- attention scores: Q hi/lo split x raw-tf32 K (2 mmas) ----------------
// K is pre-rounded to tf32 by k_rope, so the K-lo term vanishes exactly.
__global__ void __launch_bounds__(256, 2) k_scores_mma(
    const float* __restrict__ Qb, const float* __restrict__ Kb,
    const int* __restrict__ am, float* __restrict__ SCp) {
    int bh = blockIdx.z;
    int b = bh >> 4, h = bh & 15;
    int m0 = blockIdx.y * 128, n0 = blockIdx.x * 128;
    if (n0 > m0 + 127) return;
    float* outp = SCp + (size_t)bh * Sq * Sq;
    int tid = threadIdx.x;
    extern __shared__ float sm[];
    uint32_t sb = smem_u32(sm);
    int lane = tid & 31, wid = tid >> 5;
    int wm = wid & 1, wn = wid >> 1;
    const float* Ap = Qb + (size_t)b * Sq * Dq + (size_t)m0 * Dq + h * Dhq;
    const float* Bp = Kb + (size_t)b * Sq * Dq + (size_t)n0 * Dq + h * Dhq;

    auto issue_chunk = [&](int kt, int buf) {
        uint32_t base = sb + (uint32_t)buf * 36864u;
#pragma unroll
        for (int i = 0; i < 4; i++) {
            int fi = tid + i * 256;
            int row = fi >> 3, q = fi & 7;
            cp_async16(base + (uint32_t)((row * 36 + q * 4) * 4),
                       Ap + (size_t)row * Dq + kt + q * 4);
        }
#pragma unroll
        for (int i = 0; i < 4; i++) {
            int fi = tid + i * 256;
            int row = fi >> 3, q = fi & 7;
            cp_async16(base + 18432u + (uint32_t)((row * 36 + q * 4) * 4),
                       Bp + (size_t)row * Dq + kt + q * 4);
        }
        asm volatile("cp.async.commit_group;");
    };

    float acc[4][4][4] = {};
    int abase = (wm * 64 + (lane >> 2)) * 36 + (lane & 3);
    int bbase = (wn * 32 + (lane >> 2)) * 36 + (lane & 3);

    issue_chunk(0, 0);
    for (int c = 0; c < 4; c++) {
        if (c + 1 < 4) {
            issue_chunk((c + 1) << 5, (c + 1) & 1);
            asm volatile("cp.async.wait_group 1;");
        } else {
            asm volatile("cp.async.wait_group 0;");
        }
        __syncthreads();
        const float* sA = sm + (c & 1) * 9216;
        const float* sB = sA + 4608;
#pragma unroll
        for (int ks = 0; ks < 4; ks++) {
            uint32_t ah[4][4], al[4][4], bf[4][2];
#pragma unroll
            for (int mf = 0; mf < 4; mf++) {
                const float* p = sA + abase + mf * 576 + ks * 8;
                float x0 = p[0], x1 = p[288], x2 = p[4], x3 = p[292];
                ah[mf][0] = tf32r(x0); al[mf][0] = tf32r(x0 - __uint_as_float(ah[mf][0]));
                ah[mf][1] = tf32r(x1); al[mf][1] = tf32r(x1 - __uint_as_float(ah[mf][1]));
                ah[mf][2] = tf32r(x2); al[mf][2] = tf32r(x2 - __uint_as_float(ah[mf][2]));
                ah[mf][3] = tf32r(x3); al[mf][3] = tf32r(x3 - __uint_as_float(ah[mf][3]));
            }
#pragma unroll
            for (int nf = 0; nf < 4; nf++) {
                const float* p = sB + bbase + nf * 288 + ks * 8;
                bf[nf][0] = __float_as_uint(p[0]);   // K pre-rounded tf32
                bf[nf][1] = __float_as_uint(p[4]);
            }
#pragma unroll
            for (int mf = 0; mf < 4; mf++)
#pragma unroll
                for (int nf = 0; nf < 4; nf++) {
                    mma_tf32(acc[mf][nf], al[mf], bf[nf]);
                    mma_tf32(acc[mf][nf], ah[mf], bf[nf]);
                }
        }
        __syncthreads();
    }

    float inv = __fdiv_rn(1.0f, sqrtf((float)Dhq));
#pragma unroll
    for (int nf = 0; nf < 4; nf++) {
        int n = n0 + wn * 32 + nf * 8 + (lane & 3) * 2;
        int ok0 = am[b * Sq + n] != 0, ok1 = am[b * Sq + n + 1] != 0;
#pragma unroll
        for (int mf = 0; mf < 4; mf++) {
            int m = m0 + wm * 64 + mf * 16 + (lane >> 2);
            float* c = acc[mf][nf];
            float2 v0, v1;
            v0.x = c[0] * inv + ((n     <= m && ok0) ? 0.0f : -1e9f);
            v0.y = c[1] * inv + ((n + 1 <= m && ok1) ? 0.0f : -1e9f);
            v1.x = c[2] * inv + ((n     <= m + 8 && ok0) ? 0.0f : -1e9f);
            v1.y = c[3] * inv + ((n + 1 <= m + 8 && ok1) ? 0.0f : -1e9f);
            *(float2*)(outp + (size_t)m * Sq + n) = v0;
            *(float2*)(outp + (size_t)(m + 8) * Sq + n) = v1;
        }
    }
}

// ---------------- softmax over causal-bounded row (fast exp; stores tf32-rounded P) ----
__global__ void k_softmax(float* __restrict__ SCp) {
    int m = blockIdx.x & (Sq - 1);
    int bound = ((m >> 7) + 1) << 7;
    float* p = SCp + (size_t)blockIdx.x * Sq;
    int tid = threadIdx.x;
    float v[4];
    float mx = -3.4e38f;
#pragma unroll
    for (int i = 0; i < 4; i++) {
        int k = tid + i * 256;
        v[i] = (k < bound) ? p[k] : -3.4e38f;
        mx = fmaxf(mx, v[i]);
    }
    mx = blk_max(mx);
    float s = 0.0f;
#pragma unroll
    for (int i = 0; i < 4; i++) { v[i] = __expf(v[i] - mx); s += v[i]; }
    s = blk_sum(s);
#pragma unroll
    for (int i = 0; i < 4; i++) {
        int k = tid + i * 256;
        if (k < bound) p[k] = tf32rf(__fdiv_rn(v[i], s));
    }
}

// ---------------- ctx via mma (causal K-truncation; two-stage) ----------------
constexpr int CTX_SMEM_BYTES = 2 * 128 * 36 * 4 + 2 * 32 * 132 * 4;  // 70656

__global__ void __launch_bounds__(256, 2) k_ctx_mma(
    const float* __restrict__ P, const float* __restrict__ V, float* __restrict__ O) {
    extern __shared__ float sm[];
    uint32_t sb = smem_u32(sm);
    int bh = blockIdx.z;
    int b = bh >> 4, h = bh & 15;
    int m0 = blockIdx.y * 128;
    const float* Pp = P + (size_t)bh * Sq * Sq + (size_t)m0 * Sq;
    const float* Vp = V + (size_t)b * Sq * Dq + h * Dhq;
    float* Op = O + (size_t)b * Sq * Dq + (size_t)m0 * Dq + h * Dhq;
    int tid = threadIdx.x, lane = tid & 31, wid = tid >> 5;
    int wm = wid & 1, wn = wid >> 1;
    float* smB = sm + 2 * 128 * 36;

    auto issue_chunk = [&](int kt, int buf) {
        uint32_t abase_s = sb + (uint32_t)buf * 18432u;
        uint32_t bbase_s = sb + 36864u + (uint32_t)buf * 16896u;
#pragma unroll
        for (int i = 0; i < 4; i++) {
            int fi = tid + i * 256;
            int row = fi >> 3, q = fi & 7;
            cp_async16(abase_s + (uint32_t)((row * 36 + q * 4) * 4),
                       Pp + (size_t)row * Sq + kt + q * 4);
        }
#pragma unroll
        for (int i = 0; i < 4; i++) {
            int fi = tid + i * 256;
            int kr = fi >> 5, n4 = (fi & 31) * 4;
            cp_async16(bbase_s + (uint32_t)((kr * 132 + n4) * 4),
                       Vp + (size_t)(kt + kr) * Dq + n4);
        }
        asm volatile("cp.async.commit_group;");
    };

    float acc[4][4][4] = {};
    int abase = (wm * 64 + (lane >> 2)) * 36 + (lane & 3);

    int nch = (m0 + 128) >> 5;
    issue_chunk(0, 0);
    for (int c = 0; c < nch; c++) {
        if (c + 1 < nch) {
            issue_chunk((c + 1) << 5, (c + 1) & 1);
            asm volatile("cp.async.wait_group 1;");
        } else {
            asm volatile("cp.async.wait_group 0;");
        }
        __syncthreads();
        const float* sA = sm + (c & 1) * 4608;
        const float* sB = smB + (c & 1) * 4224;
#pragma unroll
        for (int ks = 0; ks < 4; ks++) {
            uint32_t af[4][4], bf[4][2];
#pragma unroll
            for (int mf = 0; mf < 4; mf++) {
                const float* p = sA + abase + mf * 576 + ks * 8;
                af[mf][0] = __float_as_uint(p[0]);
                af[mf][1] = __float_as_uint(p[288]);
                af[mf][2] = __float_as_uint(p[4]);
                af[mf][3] = __float_as_uint(p[292]);
            }
#pragma unroll
            for (int nf = 0; nf < 4; nf++) {
                int n = wn * 32 + nf * 8 + (lane >> 2);
                const float* p = sB + (ks * 8 + (lane & 3)) * 132 + n;
                bf[nf][0] = __float_as_uint(p[0]);
                bf[nf][1] = __float_as_uint(p[4 * 132]);
            }
#pragma unroll
            for (int mf = 0; mf < 4; mf++)
#pragma unroll
                for (int nf = 0; nf < 4; nf++) mma_tf32(acc[mf][nf], af[mf], bf[nf]);
        }
        __syncthreads();
    }

#pragma unroll
    for (int nf = 0; nf < 4; nf++) {
        int n = wn * 32 + nf * 8 + (lane & 3) * 2;
#pragma unroll
        for (int mf = 0; mf < 4; mf++) {
            int m = wm * 64 + mf * 16 + (lane >> 2);
            float* c = acc[mf][nf];
            *(float2*)(Op + (size_t)m * Dq + n) = make_float2(tf32rf(c[0]), tf32rf(c[1]));
            *(float2*)(Op + (size_t)(m + 8) * Dq + n) = make_float2(tf32rf(c[2]), tf32rf(c[3]));
        }
    }
}

// ---------------- rope tables (fp64 math, computed once) ----------------
__global__ void k_ropetab(float* __restrict__ ct, float* __restrict__ st) {
    int idx = blockIdx.x * blockDim.x + threadIdx.x;
    if (idx >= Sq * 64) return;
    int i = idx & 63;
    int pos = idx >> 6;
    double invf = exp(-((double)i / 64.0) * log(10000.0));
    double f = (double)pos * invf;
    double sd, cd;
    sincos(f, &sd, &cd);
    ct[idx] = (float)cd;
    st[idx] = (float)sd;
}

// ---------------- rope applying cached tables; K written tf32-rounded ----------------
__global__ void k_rope(float* __restrict__ Qb, float* __restrict__ Kb,
                       const float* __restrict__ ct, const float* __restrict__ st) {
    int idx = blockIdx.x * blockDim.x + threadIdx.x;
    if (idx >= Mq * Hq * 64) return;
    int i = idx & 63;
    int h = (idx >> 6) & 15;
    int m = idx >> 10;
    int pos = m & (Sq - 1);
    float c = ct[pos * 64 + i], s = st[pos * 64 + i];
    size_t base = (size_t)m * Dq + (size_t)h * Dhq + i;
    float q1 = Qb[base], q2 = Qb[base + 64];
    Qb[base]      = q1 * c - q2 * s;
    Qb[base + 64] = q2 * c + q1 * s;
    float k1 = Kb[base], k2 = Kb[base + 64];
    Kb[base]      = tf32rf(k1 * c - k2 * s);   // scores B-side consumes raw tf32
    Kb[base + 64] = tf32rf(k2 * c + k1 * s);
}

// ---------------- copy ----------------
__global__ void k_copy4(const float4* __restrict__ a, float4* __restrict__ b, int n) {
    int i = blockIdx.x * blockDim.x + threadIdx.x;
    if (i < n) b[i] = a[i];
}

// ---------------- host launcher ----------------
extern "C" void kernel_launch(void* const* d_in, const int* in_sizes, int n_in,
                              void* d_out, int out_size) {
    const float* inputs = (const float*)d_in[0];
    const int*   amask  = (const int*)d_in[1];
    const float* wq = (const float*)d_in[2];
    const float* aq = (const float*)d_in[3];
    const float* bq = (const float*)d_in[4];
    const float* wk = (const float*)d_in[5];
    const float* ak = (const float*)d_in[6];
    const float* bk = (const float*)d_in[7];
    const float* wv = (const float*)d_in[8];
    const float* av = (const float*)d_in[9];
    const float* bv = (const float*)d_in[10];
    const float* wo = (const float*)d_in[11];
    const float* ao = (const float*)d_in[12];
    const float* bo = (const float*)d_in[13];
    const float* ln1 = (const float*)d_in[14];
    const float* wg = (const float*)d_in[15];
    const float* wu = (const float*)d_in[16];
    const float* wd = (const float*)d_in[17];
    const float* ln2 = (const float*)d_in[18];
    const float* norm_f = (const float*)d_in[19];

    float* gs = nullptr;
    cudaGetSymbolAddress((void**)&gs, g_scratch);

    float* dWQKV = gs + OFF_WQKV;
    float* dWO = gs + OFF_WO;
    float* dWG = gs + OFF_WG;  float* dWU = gs + OFF_WU;  float* dWD = gs + OFF_WD;
    float* X   = gs + OFF_X;   float* Hb  = gs + OFF_H;
    float* Qb  = gs + OFF_Q;   float* Kb  = gs + OFF_K;   float* Vb = gs + OFF_V;
    float* Cb  = gs + OFF_C;   float* SC  = gs + OFF_S;
    float* Gb  = gs + OFF_G;
    float* Tq  = gs + OFF_T;
    float* Tk  = Tq + (size_t)Mq * Rq;
    float* Tv  = Tk + (size_t)Mq * Rq;
    float* To  = Tv + (size_t)Mq * Rq;
    float* Ct  = gs + OFF_RT;
    float* St  = Ct + (size_t)Sq * 64;

    cudaFuncSetAttribute(k_gemm_mma, cudaFuncAttributeMaxDynamicSharedMemorySize,
                         MMA_SMEM_BYTES);
    cudaFuncSetAttribute(k_scores_mma, cudaFuncAttributeMaxDynamicSharedMemorySize,
                         MMA_SMEM_BYTES);
    cudaFuncSetAttribute(k_ctx_mma, cudaFuncAttributeMaxDynamicSharedMemorySize,
                         CTX_SMEM_BYTES);

    k_ropetab<<<(Sq * 64 + 255) / 256, 256>>>(Ct, St);

    {
        int nb = (int)(DD / 64), nw = (nb + 3) / 4, g = (nw + 7) / 8;
        for (int l = 0; l < Lq; l++) {
            k_dequant<<<g, 256>>>(wq + (size_t)l * DD, dWQKV + (size_t)l * 3 * DD, nb);
            k_dequant<<<g, 256>>>(wk + (size_t)l * DD, dWQKV + (size_t)l * 3 * DD + DD, nb);
            k_dequant<<<g, 256>>>(wv + (size_t)l * DD, dWQKV + (size_t)l * 3 * DD + 2 * DD, nb);
        }
        int nbo = (int)(Lq * DD / 64), nwo = (nbo + 3) / 4;
        k_dequant<<<(nwo + 7) / 8, 256>>>(wo, dWO, nbo);
        int nbf = (int)(Lq * FD / 64), nwf = (nbf + 3) / 4;
        k_dequant<<<(nwf + 7) / 8, 256>>>(wg, dWG, nbf);
        k_dequant<<<(nwf + 7) / 8, 256>>>(wu, dWU, nbf);
        k_dequant<<<(nwf + 7) / 8, 256>>>(wd, dWD, nbf);
    }

    k_copy4<<<(int)(MD / 4 / 256), 256>>>((const float4*)inputs, (float4*)X, (int)(MD / 4));

    dim3 gQKV(3 * Dq / 128, Mq / 128);
    dim3 gDD(Dq / 128, Mq / 128);
    dim3 gFD(Fq / 128, Mq / 128);
    dim3 gSC(Sq / 128, Sq / 128, Bq * Hq);
    dim3 gCX(1, Sq / 128, Bq * Hq);

    for (int l = 0; l < Lq; l++) {
        const float* aqL = aq + (size_t)l * Rq * Dq;
        const float* bqL = bq + (size_t)l * Dq * Rq;
        const float* akL = ak + (size_t)l * Rq * Dq;
        const float* bkL = bk + (size_t)l * Dq * Rq;
        const float* avL = av + (size_t)l * Rq * Dq;
        const float* bvL = bv + (size_t)l * Dq * Rq;
        const float* aoL = ao + (size_t)l * Rq * Dq;
        const float* boL = bo + (size_t)l * Dq * Rq;
        const float* WQKVl = dWQKV + (size_t)l * 3 * DD;
        const float* WOl = dWO + (size_t)l * DD;
        const float* WGl = dWG + (size_t)l * FD;
        const float* WUl = dWU + (size_t)l * FD;
        const float* WDl = dWD + (size_t)l * FD;

        k_rmsnorm_lora<<<Mq, 256>>>(X, ln1 + (size_t)l * Dq, aqL, akL, avL,
                                    Hb, Tq, Tk, Tv);

        k_gemm_mma<<<gQKV, 256, MMA_SMEM_BYTES>>>(Hb, WQKVl, Tq, bqL, bkL, bvL,
                                                  nullptr, Qb, Dq, Dq, 1, 0, 0, 1);

        k_rope<<<(Mq * Hq * 64 + 255) / 256, 256>>>(Qb, Kb, Ct, St);

        k_scores_mma<<<gSC, 256, MMA_SMEM_BYTES>>>(Qb, Kb, amask, SC);
        k_softmax<<<Bq * Hq * Sq, 256>>>(SC);
        k_ctx_mma<<<gCX, 256, CTX_SMEM_BYTES>>>(SC, Vb, Cb);

        k_lora_t<<<Mq, 256>>>(Cb, aoL, To);
        k_gemm_mma<<<gDD, 256, MMA_SMEM_BYTES>>>(Cb, WOl, To, boL, nullptr, nullptr,
                                                 nullptr, X, Dq, Dq, 1, 1, 0, 0);

        k_rmsnorm<<<Mq, 256>>>(X, ln2 + (size_t)l * Dq, Hb, 1);
        k_gemm_mma<<<gFD, 256, MMA_SMEM_BYTES>>>(Hb, WGl, nullptr, nullptr, nullptr, nullptr,
                                                 nullptr, Gb, Fq, Dq, 0, 0, 0, 0);
        k_gemm_mma<<<gFD, 256, MMA_SMEM_BYTES>>>(Hb, WUl, nullptr, nullptr, nullptr, nullptr,
                                                 Gb, Gb, Fq, Dq, 0, 0, 1, 0);
        k_gemm_mma<<<gDD, 256, MMA_SMEM_BYTES>>>(Gb, WDl, nullptr, nullptr, nullptr, nullptr,
                                                 nullptr, X, Dq, Fq, 0, 1, 0, 0);
    }

    k_rmsnorm<<<Mq, 256>>>(X, norm_f, (float*)d_out, 0);
}

// round 17
// speedup vs baseline: 1.0111x; 1.0111x over previous
#include <cuda_runtime.h>
#include <cstdint>
#include <math.h>

// ---------------- problem constants ----------------
constexpr int Bq = 2, Sq = 1024, Dq = 2048, Hq = 16, Dhq = 128, Fq = 5504, Rq = 8, Lq = 2;
constexpr int Mq = Bq * Sq;  // 2048 tokens

constexpr size_t DD  = (size_t)Dq * Dq;
constexpr size_t FD  = (size_t)Fq * Dq;
constexpr size_t MD  = (size_t)Mq * Dq;
constexpr size_t MF  = (size_t)Mq * Fq;
constexpr size_t SCN = (size_t)Bq * Hq * Sq * Sq;

constexpr size_t OFF_WQKV = 0;                                   // [L][3D][D]
constexpr size_t OFF_WO = OFF_WQKV + (size_t)Lq * 3 * DD;
constexpr size_t OFF_WG = OFF_WO + (size_t)Lq * DD;
constexpr size_t OFF_WU = OFF_WG + (size_t)Lq * FD;
constexpr size_t OFF_WD = OFF_WU + (size_t)Lq * FD;
constexpr size_t OFF_X  = OFF_WD + (size_t)Lq * FD;
constexpr size_t OFF_H  = OFF_X + MD;
constexpr size_t OFF_Q  = OFF_H + MD;
constexpr size_t OFF_K  = OFF_Q + MD;
constexpr size_t OFF_V  = OFF_K + MD;
constexpr size_t OFF_C  = OFF_V + MD;
constexpr size_t OFF_S  = OFF_C + MD;
constexpr size_t OFF_G  = OFF_S + SCN;
constexpr size_t OFF_U  = OFF_G + MF;
constexpr size_t OFF_T  = OFF_U + MF;
constexpr size_t OFF_RT = OFF_T + (size_t)Mq * Rq * 4;
constexpr size_t SCRATCH_TOTAL = OFF_RT + (size_t)2 * Sq * 64;

__device__ float g_scratch[SCRATCH_TOTAL];

// ---------------- NF4 tables ----------------
__device__ __constant__ float NF4C[16] = {
    -1.0f, -0.6961928009986877f, -0.5250730514526367f, -0.39491748809814453f,
    -0.28444138169288635f, -0.18477343022823334f, -0.09105003625154495f, 0.0f,
    0.07958029955625534f, 0.16093020141124725f, 0.24611230194568634f,
    0.33791524171829224f, 0.44070982933044434f, 0.5626170039176941f,
    0.7229568362236023f, 1.0f};

__device__ __constant__ float NF4M[15] = {
    (-1.0f + -0.6961928009986877f) * 0.5f,
    (-0.6961928009986877f + -0.5250730514526367f) * 0.5f,
    (-0.5250730514526367f + -0.39491748809814453f) * 0.5f,
    (-0.39491748809814453f + -0.28444138169288635f) * 0.5f,
    (-0.28444138169288635f + -0.18477343022823334f) * 0.5f,
    (-0.18477343022823334f + -0.09105003625154495f) * 0.5f,
    (-0.09105003625154495f + 0.0f) * 0.5f,
    (0.0f + 0.07958029955625534f) * 0.5f,
    (0.07958029955625534f + 0.16093020141124725f) * 0.5f,
    (0.16093020141124725f + 0.24611230194568634f) * 0.5f,
    (0.24611230194568634f + 0.33791524171829224f) * 0.5f,
    (0.33791524171829224f + 0.44070982933044434f) * 0.5f,
    (0.44070982933044434f + 0.5626170039176941f) * 0.5f,
    (0.5626170039176941f + 0.7229568362236023f) * 0.5f,
    (0.7229568362236023f + 1.0f) * 0.5f};

__device__ __forceinline__ uint32_t tf32r(float x) {
    uint32_t r;
    asm("cvt.rna.tf32.f32 %0, %1;" : "=r"(r) : "f"(x));
    return r;
}
__device__ __forceinline__ float tf32rf(float x) {
    return __uint_as_float(tf32r(x));
}

// ---------------- unified dequant: ALL weight regions in ONE launch ----------------
// Region sizes are multiples of 4 blocks-of-64, so one warp (4 blocks) never straddles.
constexpr int NSEG = 10;
struct DQTab {
    const float* src[NSEG];
    float* dst[NSEG];
    int cum[NSEG + 1];   // cumulative block counts
};

__global__ void k_dequant_all(DQTab tab) {
    int warp = blockIdx.x * (blockDim.x >> 5) + (threadIdx.x >> 5);
    int lane = threadIdx.x & 31;
    int blk = warp * 4 + (lane >> 3);
    if (blk >= tab.cum[NSEG]) return;
    int seg = 0;
#pragma unroll
    for (int i = 1; i < NSEG; i++) seg += (blk >= tab.cum[i]) ? 1 : 0;
    int lblk = blk - tab.cum[seg];
    const float* w = tab.src[seg];
    float* o = tab.dst[seg];
    int sub = lane & 7;
    const float4* p = (const float4*)(w + (size_t)lblk * 64);
    float4 v0 = p[sub], v1 = p[sub + 8];
    float am = fmaxf(fmaxf(fabsf(v0.x), fabsf(v0.y)), fmaxf(fabsf(v0.z), fabsf(v0.w)));
    am = fmaxf(am, fmaxf(fmaxf(fabsf(v1.x), fabsf(v1.y)), fmaxf(fabsf(v1.z), fabsf(v1.w))));
#pragma unroll
    for (int s = 4; s; s >>= 1) am = fmaxf(am, __shfl_xor_sync(0xffffffffu, am, s));
    float d = fmaxf(am, 1e-12f);
    float t[15];
#pragma unroll
    for (int i = 0; i < 15; i++) t[i] = NF4M[i] * d;
    auto code = [&](float v) -> float {
        int idx = 0;
#pragma unroll
        for (int i = 0; i < 15; i++) idx += (v > t[i]) ? 1 : 0;
        return tf32rf(NF4C[idx] * am);
    };
    float4 q0, q1;
    q0.x = code(v0.x); q0.y = code(v0.y); q0.z = code(v0.z); q0.w = code(v0.w);
    q1.x = code(v1.x); q1.y = code(v1.y); q1.z = code(v1.z); q1.w = code(v1.w);
    float4* op = (float4*)(o + (size_t)lblk * 64);
    op[sub] = q0; op[sub + 8] = q1;
}

// ---------------- block reductions (blockDim = 256) ----------------
__device__ __forceinline__ float blk_sum(float v) {
    __shared__ float sh_s[8];
#pragma unroll
    for (int s = 16; s; s >>= 1) v += __shfl_xor_sync(0xffffffffu, v, s);
    if ((threadIdx.x & 31) == 0) sh_s[threadIdx.x >> 5] = v;
    __syncthreads();
    if (threadIdx.x < 32) {
        v = (threadIdx.x < 8) ? sh_s[threadIdx.x] : 0.0f;
#pragma unroll
        for (int s = 4; s; s >>= 1) v += __shfl_xor_sync(0xffffffffu, v, s);
        if (threadIdx.x == 0) sh_s[0] = v;
    }
    __syncthreads();
    float r = sh_s[0];
    __syncthreads();
    return r;
}

__device__ __forceinline__ float blk_max(float v) {
    __shared__ float sh_m[8];
#pragma unroll
    for (int s = 16; s; s >>= 1) v = fmaxf(v, __shfl_xor_sync(0xffffffffu, v, s));
    if ((threadIdx.x & 31) == 0) sh_m[threadIdx.x >> 5] = v;
    __syncthreads();
    if (threadIdx.x < 32) {
        v = (threadIdx.x < 8) ? sh_m[threadIdx.x] : -3.4e38f;
#pragma unroll
        for (int s = 4; s; s >>= 1) v = fmaxf(v, __shfl_xor_sync(0xffffffffu, v, s));
        if (threadIdx.x == 0) sh_m[0] = v;
    }
    __syncthreads();
    float r = sh_m[0];
    __syncthreads();
    return r;
}

// ---------------- plain rmsnorm (rnd: write tf32-rounded for GEMM A-side) ----------------
__global__ void k_rmsnorm(const float* __restrict__ x, const float* __restrict__ w,
                          float* __restrict__ o, int rnd) {
    int row = blockIdx.x;
    const float* p = x + (size_t)row * Dq;
    float s = 0.0f;
#pragma unroll
    for (int i = threadIdx.x; i < Dq; i += 256) { float v = p[i]; s += v * v; }
    s = blk_sum(s);
    float mean = s * (1.0f / (float)Dq);
    float r = (float)(1.0 / sqrt((double)mean + 1e-5));
#pragma unroll
    for (int i = threadIdx.x; i < Dq; i += 256) {
        float hv = (p[i] * r) * w[i];
        o[(size_t)row * Dq + i] = rnd ? tf32rf(hv) : hv;
    }
}

// ---------------- fused rmsnorm + 3x lora-t (qkv); h written tf32-rounded ----------------
__global__ void k_rmsnorm_lora(
    const float* __restrict__ x, const float* __restrict__ w,
    const float* __restrict__ A0, const float* __restrict__ A1, const float* __restrict__ A2,
    float* __restrict__ h, float* __restrict__ t0, float* __restrict__ t1,
    float* __restrict__ t2) {
    __shared__ float sx[Dq];
    __shared__ float sh2[8][Rq];
    int row = blockIdx.x, tid = threadIdx.x;
    const float* p = x + (size_t)row * Dq;
    float s = 0.0f;
#pragma unroll
    for (int i = tid; i < Dq; i += 256) { float v = p[i]; sx[i] = v; s += v * v; }
    s = blk_sum(s);
    float mean = s * (1.0f / (float)Dq);
    float r = (float)(1.0 / sqrt((double)mean + 1e-5));
#pragma unroll
    for (int i = tid; i < Dq; i += 256) {
        float hv = (sx[i] * r) * w[i];
        sx[i] = hv;
        h[(size_t)row * Dq + i] = tf32rf(hv);
    }
    __syncthreads();
    const float* As[3] = {A0, A1, A2};
    float* ts[3] = {t0, t1, t2};
#pragma unroll
    for (int mt = 0; mt < 3; mt++) {
        const float* A = As[mt];
        float acc[Rq] = {};
        for (int k = tid; k < Dq; k += 256) {
            float xv = sx[k];
#pragma unroll
            for (int rr = 0; rr < Rq; rr++) acc[rr] += xv * A[(size_t)rr * Dq + k];
        }
#pragma unroll
        for (int rr = 0; rr < Rq; rr++) {
            float v = acc[rr];
#pragma unroll
            for (int s2 = 16; s2; s2 >>= 1) v += __shfl_xor_sync(0xffffffffu, v, s2);
            if ((tid & 31) == 0) sh2[tid >> 5][rr] = v;
        }
        __syncthreads();
        if (tid < Rq) {
            float v = 0.0f;
#pragma unroll
            for (int w2 = 0; w2 < 8; w2++) v += sh2[w2][tid];
            ts[mt][(size_t)row * Rq + tid] = v;
        }
        __syncthreads();
    }
}

// ---------------- lora t = x @ A^T (o-proj) ----------------
__global__ void k_lora_t(const float* __restrict__ x, const float* __restrict__ A,
                         float* __restrict__ t) {
    int m = blockIdx.x;
    const float* xr = x + (size_t)m * Dq;
    float acc[Rq] = {};
    for (int k = threadIdx.x; k < Dq; k += 256) {
        float xv = xr[k];
#pragma unroll
        for (int r = 0; r < Rq; r++) acc[r] += xv * A[(size_t)r * Dq + k];
    }
    __shared__ float sh[8][Rq];
#pragma unroll
    for (int r = 0; r < Rq; r++) {
        float v = acc[r];
#pragma unroll
        for (int s = 16; s; s >>= 1) v += __shfl_xor_sync(0xffffffffu, v, s);
        if ((threadIdx.x & 31) == 0) sh[threadIdx.x >> 5][r] = v;
    }
    __syncthreads();
    if (threadIdx.x < Rq) {
        float v = 0.0f;
#pragma unroll
        for (int w2 = 0; w2 < 8; w2++) v += sh[w2][threadIdx.x];
        t[(size_t)m * Rq + threadIdx.x] = v;
    }
}

// ================= tf32 mma helpers =================
__device__ __forceinline__ uint32_t smem_u32(const void* p) {
    uint32_t a;
    asm("{ .reg .u64 t; cvta.to.shared.u64 t, %1; cvt.u32.u64 %0, t; }" : "=r"(a) : "l"(p));
    return a;
}
__device__ __forceinline__ void mma_tf32(float* c, const uint32_t* a, const uint32_t* b) {
    asm volatile(
        "mma.sync.aligned.m16n8k8.row.col.f32.tf32.tf32.f32 "
        "{%0,%1,%2,%3},{%4,%5,%6,%7},{%8,%9},{%0,%1,%2,%3};"
        : "+f"(c[0]), "+f"(c[1]), "+f"(c[2]), "+f"(c[3])
        : "r"(a[0]), "r"(a[1]), "r"(a[2]), "r"(a[3]), "r"(b[0]), "r"(b[1]));
}
__device__ __forceinline__ void cp_async16(uint32_t dst, const float* src) {
    asm volatile("cp.async.cg.shared.global [%0], [%1], 16;"
                 :: "r"(dst), "l"(__cvta_generic_to_global(src)));
}

// ---------------- main linear GEMM (two-stage + fused-QKV mode + resid source) --------
constexpr int MMA_SMEM_BYTES = 2 * 2 * 128 * 36 * 4;  // 73728

__global__ void __launch_bounds__(256, 2) k_gemm_mma(
    const float* __restrict__ A, const float* __restrict__ W,
    const float* TL, const float* BL0, const float* BL1, const float* BL2,
    const float* __restrict__ gate, const float* __restrict__ rsrc,
    float* out, int N2, int K2, int lora, int resid, int rnd, int qkv) {
    extern __shared__ float sm[];
    uint32_t sb = smem_u32(sm);
    int tid = threadIdx.x, lane = tid & 31, wid = tid >> 5;
    int wm = wid & 1, wn = wid >> 1;
    int m0 = blockIdx.y * 128, n0 = blockIdx.x * 128;
    const float* Ap = A + (size_t)m0 * K2;
    const float* Wp = W + (size_t)n0 * K2;

    const float* BL = BL0;
    int nloc0 = n0;
    if (qkv) {
        int seg = blockIdx.x >> 4;
        nloc0 = n0 - seg * 2048;
        TL += (size_t)seg * Mq * Rq;
        BL = (seg == 0) ? BL0 : ((seg == 1) ? BL1 : BL2);
        rnd = (seg == 2) ? 1 : 0;
        out += (size_t)seg * MD;
    }

    auto issue_chunk = [&](int kt, int buf) {
        uint32_t base = sb + (uint32_t)buf * 36864u;
#pragma unroll
        for (int i = 0; i < 4; i++) {
            int fi = tid + i * 256;
            int row = fi >> 3, q = fi & 7;
            cp_async16(base + (uint32_t)((row * 36 + q * 4) * 4),
                       Ap + (size_t)row * K2 + kt + q * 4);
        }
#pragma unroll
        for (int i = 0; i < 4; i++) {
            int fi = tid + i * 256;
            int row = fi >> 3, q = fi & 7;
            cp_async16(base + 18432u + (uint32_t)((row * 36 + q * 4) * 4),
                       Wp + (size_t)row * K2 + kt + q * 4);
        }
        asm volatile("cp.async.commit_group;");
    };

    float acc[4][4][4] = {};
    int abase = (wm * 64 + (lane >> 2)) * 36 + (lane & 3);
    int bbase = (wn * 32 + (lane >> 2)) * 36 + (lane & 3);

    int nch = K2 >> 5;
    issue_chunk(0, 0);
    for (int c = 0; c < nch; c++) {
        if (c + 1 < nch) {
            issue_chunk((c + 1) << 5, (c + 1) & 1);
            asm volatile("cp.async.wait_group 1;");
        } else {
            asm volatile("cp.async.wait_group 0;");
        }
        __syncthreads();
        const float* sA = sm + (c & 1) * 9216;
        const float* sB = sA + 4608;
#pragma unroll
        for (int ks = 0; ks < 4; ks++) {
            uint32_t af[4][4], bf[4][2];
#pragma unroll
            for (int mf = 0; mf < 4; mf++) {
                const float* p = sA + abase + mf * 576 + ks * 8;
                af[mf][0] = __float_as_uint(p[0]);
                af[mf][1] = __float_as_uint(p[288]);
                af[mf][2] = __float_as_uint(p[4]);
                af[mf][3] = __float_as_uint(p[292]);
            }
#pragma unroll
            for (int nf = 0; nf < 4; nf++) {
                const float* p = sB + bbase + nf * 288 + ks * 8;
                bf[nf][0] = __float_as_uint(p[0]);
                bf[nf][1] = __float_as_uint(p[4]);
            }
#pragma unroll
            for (int mf = 0; mf < 4; mf++)
#pragma unroll
                for (int nf = 0; nf < 4; nf++) mma_tf32(acc[mf][nf], af[mf], bf[nf]);
        }
        __syncthreads();
    }

#pragma unroll
    for (int nf = 0; nf < 4; nf++) {
        int n = nloc0 + wn * 32 + nf * 8 + (lane & 3) * 2;
        float bl0[8], bl1[8];
        if (lora) {
            *(float4*)bl0       = *(const float4*)(BL + (size_t)n * 8);
            *(float4*)(bl0 + 4) = *(const float4*)(BL + (size_t)n * 8 + 4);
            *(float4*)bl1       = *(const float4*)(BL + (size_t)(n + 1) * 8);
            *(float4*)(bl1 + 4) = *(const float4*)(BL + (size_t)(n + 1) * 8 + 4);
        }
#pragma unroll
        for (int mf = 0; mf < 4; mf++) {
            int m = m0 + wm * 64 + mf * 16 + (lane >> 2);
            float* c = acc[mf][nf];
            float c0 = c[0], c1 = c[1], c2 = c[2], c3 = c[3];
            if (lora) {
                float tl[8];
                *(float4*)tl       = *(const float4*)(TL + (size_t)m * 8);
                *(float4*)(tl + 4) = *(const float4*)(TL + (size_t)m * 8 + 4);
                float d0 = 0.0f, d1 = 0.0f;
#pragma unroll
                for (int r = 0; r < 8; r++) { d0 += tl[r] * bl0[r]; d1 += tl[r] * bl1[r]; }
                c0 += 2.0f * d0; c1 += 2.0f * d1;
                float tl2[8];
                *(float4*)tl2       = *(const float4*)(TL + (size_t)(m + 8) * 8);
                *(float4*)(tl2 + 4) = *(const float4*)(TL + (size_t)(m + 8) * 8 + 4);
                float e0 = 0.0f, e1 = 0.0f;
#pragma unroll
                for (int r = 0; r < 8; r++) { e0 += tl2[r] * bl0[r]; e1 += tl2[r] * bl1[r]; }
                c2 += 2.0f * e0; c3 += 2.0f * e1;
            }
            if (gate) {
                float2 g0 = *(const float2*)(gate + (size_t)m * N2 + n);
                float2 g1 = *(const float2*)(gate + (size_t)(m + 8) * N2 + n);
                float s0 = __fdiv_rn(1.0f, 1.0f + __expf(-g0.x));
                float s1 = __fdiv_rn(1.0f, 1.0f + __expf(-g0.y));
                float s2 = __fdiv_rn(1.0f, 1.0f + __expf(-g1.x));
                float s3 = __fdiv_rn(1.0f, 1.0f + __expf(-g1.y));
                c0 = (g0.x * s0) * c0; c1 = (g0.y * s1) * c1;
                c2 = (g1.x * s2) * c2; c3 = (g1.y * s3) * c3;
            }
            float* o0 = out + (size_t)m * N2 + n;
            float* o1 = out + (size_t)(m + 8) * N2 + n;
            if (resid) {
                const float* r0p = rsrc + (size_t)m * N2 + n;
                const float* r1p = rsrc + (size_t)(m + 8) * N2 + n;
                float2 r0 = *(const float2*)r0p;
                float2 r1 = *(const float2*)r1p;
                c0 += r0.x; c1 += r0.y; c2 += r1.x; c3 += r1.y;
            }
            if (rnd) {
                c0 = tf32rf(c0); c1 = tf32rf(c1); c2 = tf32rf(c2); c3 = tf32rf(c3);
            }
            *(float2*)o0 = make_float2(c0, c1);
            *(float2*)o1 = make_float2(c2, c3);
        }
    }
}

// ---------------- attention scores: Q hi/lo split x raw-tf32 K (2 mmas) ----------------
__global__ void __launch_bounds__(256, 2) k_scores_mma(
    const float* __restrict__ Qb, const float* __restrict__ Kb,
    const int* __restrict__ am, float* __restrict__ SCp) {
    int bh = blockIdx.z;
    int b = bh >> 4, h = bh & 15;
    int m0 = blockIdx.y * 128, n0 = blockIdx.x * 128;
    if (n0 > m0 + 127) return;
    float* outp = SCp + (size_t)bh * Sq * Sq;
    int tid = threadIdx.x;
    extern __shared__ float sm[];
    uint32_t sb = smem_u32(sm);
    int lane = tid & 31, wid = tid >> 5;
    int wm = wid & 1, wn = wid >> 1;
    const float* Ap = Qb + (size_t)b * Sq * Dq + (size_t)m0 * Dq + h * Dhq;
    const float* Bp = Kb + (size_t)b * Sq * Dq + (size_t)n0 * Dq + h * Dhq;

    auto issue_chunk = [&](int kt, int buf) {
        uint32_t base = sb + (uint32_t)buf * 36864u;
#pragma unroll
        for (int i = 0; i < 4; i++) {
            int fi = tid + i * 256;
            int row = fi >> 3, q = fi & 7;
            cp_async16(base + (uint32_t)((row * 36 + q * 4) * 4),
                       Ap + (size_t)row * Dq + kt + q * 4);
        }
#pragma unroll
        for (int i = 0; i < 4; i++) {
            int fi = tid + i * 256;
            int row = fi >> 3, q = fi & 7;
            cp_async16(base + 18432u + (uint32_t)((row * 36 + q * 4) * 4),
                       Bp + (size_t)row * Dq + kt + q * 4);
        }
        asm volatile("cp.async.commit_group;");
    };

    float acc[4][4][4] = {};
    int abase = (wm * 64 + (lane >> 2)) * 36 + (lane & 3);
    int bbase = (wn * 32 + (lane >> 2)) * 36 + (lane & 3);

    issue_chunk(0, 0);
    for (int c = 0; c < 4; c++) {
        if (c + 1 < 4) {
            issue_chunk((c + 1) << 5, (c + 1) & 1);
            asm volatile("cp.async.wait_group 1;");
        } else {
            asm volatile("cp.async.wait_group 0;");
        }
        __syncthreads();
        const float* sA = sm + (c & 1) * 9216;
        const float* sB = sA + 4608;
#pragma unroll
        for (int ks = 0; ks < 4; ks++) {
            uint32_t ah[4][4], al[4][4], bf[4][2];
#pragma unroll
            for (int mf = 0; mf < 4; mf++) {
                const float* p = sA + abase + mf * 576 + ks * 8;
                float x0 = p[0], x1 = p[288], x2 = p[4], x3 = p[292];
                ah[mf][0] = tf32r(x0); al[mf][0] = tf32r(x0 - __uint_as_float(ah[mf][0]));
                ah[mf][1] = tf32r(x1); al[mf][1] = tf32r(x1 - __uint_as_float(ah[mf][1]));
                ah[mf][2] = tf32r(x2); al[mf][2] = tf32r(x2 - __uint_as_float(ah[mf][2]));
                ah[mf][3] = tf32r(x3); al[mf][3] = tf32r(x3 - __uint_as_float(ah[mf][3]));
            }
#pragma unroll
            for (int nf = 0; nf < 4; nf++) {
                const float* p = sB + bbase + nf * 288 + ks * 8;
                bf[nf][0] = __float_as_uint(p[0]);
                bf[nf][1] = __float_as_uint(p[4]);
            }
#pragma unroll
            for (int mf = 0; mf < 4; mf++)
#pragma unroll
                for (int nf = 0; nf < 4; nf++) {
                    mma_tf32(acc[mf][nf], al[mf], bf[nf]);
                    mma_tf32(acc[mf][nf], ah[mf], bf[nf]);
                }
        }
        __syncthreads();
    }

    float inv = __fdiv_rn(1.0f, sqrtf((float)Dhq));
#pragma unroll
    for (int nf = 0; nf < 4; nf++) {
        int n = n0 + wn * 32 + nf * 8 + (lane & 3) * 2;
        int ok0 = am[b * Sq + n] != 0, ok1 = am[b * Sq + n + 1] != 0;
#pragma unroll
        for (int mf = 0; mf < 4; mf++) {
            int m = m0 + wm * 64 + mf * 16 + (lane >> 2);
            float* c = acc[mf][nf];
            float2 v0, v1;
            v0.x = c[0] * inv + ((n     <= m && ok0) ? 0.0f : -1e9f);
            v0.y = c[1] * inv + ((n + 1 <= m && ok1) ? 0.0f : -1e9f);
            v1.x = c[2] * inv + ((n     <= m + 8 && ok0) ? 0.0f : -1e9f);
            v1.y = c[3] * inv + ((n + 1 <= m + 8 && ok1) ? 0.0f : -1e9f);
            *(float2*)(outp + (size_t)m * Sq + n) = v0;
            *(float2*)(outp + (size_t)(m + 8) * Sq + n) = v1;
        }
    }
}

// ---------------- softmax over causal-bounded row (fast exp; stores tf32-rounded P) ----
__global__ void k_softmax(float* __restrict__ SCp) {
    int m = blockIdx.x & (Sq - 1);
    int bound = ((m >> 7) + 1) << 7;
    float* p = SCp + (size_t)blockIdx.x * Sq;
    int tid = threadIdx.x;
    float v[4];
    float mx = -3.4e38f;
#pragma unroll
    for (int i = 0; i < 4; i++) {
        int k = tid + i * 256;
        v[i] = (k < bound) ? p[k] : -3.4e38f;
        mx = fmaxf(mx, v[i]);
    }
    mx = blk_max(mx);
    float s = 0.0f;
#pragma unroll
    for (int i = 0; i < 4; i++) { v[i] = __expf(v[i] - mx); s += v[i]; }
    s = blk_sum(s);
#pragma unroll
    for (int i = 0; i < 4; i++) {
        int k = tid + i * 256;
        if (k < bound) p[k] = tf32rf(__fdiv_rn(v[i], s));
    }
}

// ---------------- ctx via mma (causal K-truncation; two-stage) ----------------
constexpr int CTX_SMEM_BYTES = 2 * 128 * 36 * 4 + 2 * 32 * 132 * 4;  // 70656

__global__ void __launch_bounds__(256, 2) k_ctx_mma(
    const float* __restrict__ P, const float* __restrict__ V, float* __restrict__ O) {
    extern __shared__ float sm[];
    uint32_t sb = smem_u32(sm);
    int bh = blockIdx.z;
    int b = bh >> 4, h = bh & 15;
    int m0 = blockIdx.y * 128;
    const float* Pp = P + (size_t)bh * Sq * Sq + (size_t)m0 * Sq;
    const float* Vp = V + (size_t)b * Sq * Dq + h * Dhq;
    float* Op = O + (size_t)b * Sq * Dq + (size_t)m0 * Dq + h * Dhq;
    int tid = threadIdx.x, lane = tid & 31, wid = tid >> 5;
    int wm = wid & 1, wn = wid >> 1;
    float* smB = sm + 2 * 128 * 36;

    auto issue_chunk = [&](int kt, int buf) {
        uint32_t abase_s = sb + (uint32_t)buf * 18432u;
        uint32_t bbase_s = sb + 36864u + (uint32_t)buf * 16896u;
#pragma unroll
        for (int i = 0; i < 4; i++) {
            int fi = tid + i * 256;
            int row = fi >> 3, q = fi & 7;
            cp_async16(abase_s + (uint32_t)((row * 36 + q * 4) * 4),
                       Pp + (size_t)row * Sq + kt + q * 4);
        }
#pragma unroll
        for (int i = 0; i < 4; i++) {
            int fi = tid + i * 256;
            int kr = fi >> 5, n4 = (fi & 31) * 4;
            cp_async16(bbase_s + (uint32_t)((kr * 132 + n4) * 4),
                       Vp + (size_t)(kt + kr) * Dq + n4);
        }
        asm volatile("cp.async.commit_group;");
    };

    float acc[4][4][4] = {};
    int abase = (wm * 64 + (lane >> 2)) * 36 + (lane & 3);

    int nch = (m0 + 128) >> 5;
    issue_chunk(0, 0);
    for (int c = 0; c < nch; c++) {
        if (c + 1 < nch) {
            issue_chunk((c + 1) << 5, (c + 1) & 1);
            asm volatile("cp.async.wait_group 1;");
        } else {
            asm volatile("cp.async.wait_group 0;");
        }
        __syncthreads();
        const float* sA = sm + (c & 1) * 4608;
        const float* sB = smB + (c & 1) * 4224;
#pragma unroll
        for (int ks = 0; ks < 4; ks++) {
            uint32_t af[4][4], bf[4][2];
#pragma unroll
            for (int mf = 0; mf < 4; mf++) {
                const float* p = sA + abase + mf * 576 + ks * 8;
                af[mf][0] = __float_as_uint(p[0]);
                af[mf][1] = __float_as_uint(p[288]);
                af[mf][2] = __float_as_uint(p[4]);
                af[mf][3] = __float_as_uint(p[292]);
            }
#pragma unroll
            for (int nf = 0; nf < 4; nf++) {
                int n = wn * 32 + nf * 8 + (lane >> 2);
                const float* p = sB + (ks * 8 + (lane & 3)) * 132 + n;
                bf[nf][0] = __float_as_uint(p[0]);
                bf[nf][1] = __float_as_uint(p[4 * 132]);
            }
#pragma unroll
            for (int mf = 0; mf < 4; mf++)
#pragma unroll
                for (int nf = 0; nf < 4; nf++) mma_tf32(acc[mf][nf], af[mf], bf[nf]);
        }
        __syncthreads();
    }

#pragma unroll
    for (int nf = 0; nf < 4; nf++) {
        int n = wn * 32 + nf * 8 + (lane & 3) * 2;
#pragma unroll
        for (int mf = 0; mf < 4; mf++) {
            int m = wm * 64 + mf * 16 + (lane >> 2);
            float* c = acc[mf][nf];
            *(float2*)(Op + (size_t)m * Dq + n) = make_float2(tf32rf(c[0]), tf32rf(c[1]));
            *(float2*)(Op + (size_t)(m + 8) * Dq + n) = make_float2(tf32rf(c[2]), tf32rf(c[3]));
        }
    }
}

// ---------------- rope tables (fp64 math, computed once) ----------------
__global__ void k_ropetab(float* __restrict__ ct, float* __restrict__ st) {
    int idx = blockIdx.x * blockDim.x + threadIdx.x;
    if (idx >= Sq * 64) return;
    int i = idx & 63;
    int pos = idx >> 6;
    double invf = exp(-((double)i / 64.0) * log(10000.0));
    double f = (double)pos * invf;
    double sd, cd;
    sincos(f, &sd, &cd);
    ct[idx] = (float)cd;
    st[idx] = (float)sd;
}

// ---------------- rope applying cached tables; K written tf32-rounded ----------------
__global__ void k_rope(float* __restrict__ Qb, float* __restrict__ Kb,
                       const float* __restrict__ ct, const float* __restrict__ st) {
    int idx = blockIdx.x * blockDim.x + threadIdx.x;
    if (idx >= Mq * Hq * 64) return;
    int i = idx & 63;
    int h = (idx >> 6) & 15;
    int m = idx >> 10;
    int pos = m & (Sq - 1);
    float c = ct[pos * 64 + i], s = st[pos * 64 + i];
    size_t base = (size_t)m * Dq + (size_t)h * Dhq + i;
    float q1 = Qb[base], q2 = Qb[base + 64];
    Qb[base]      = q1 * c - q2 * s;
    Qb[base + 64] = q2 * c + q1 * s;
    float k1 = Kb[base], k2 = Kb[base + 64];
    Kb[base]      = tf32rf(k1 * c - k2 * s);
    Kb[base + 64] = tf32rf(k2 * c + k1 * s);
}

// ---------------- host launcher ----------------
extern "C" void kernel_launch(void* const* d_in, const int* in_sizes, int n_in,
                              void* d_out, int out_size) {
    const float* inputs = (const float*)d_in[0];
    const int*   amask  = (const int*)d_in[1];
    const float* wq = (const float*)d_in[2];
    const float* aq = (const float*)d_in[3];
    const float* bq = (const float*)d_in[4];
    const float* wk = (const float*)d_in[5];
    const float* ak = (const float*)d_in[6];
    const float* bk = (const float*)d_in[7];
    const float* wv = (const float*)d_in[8];
    const float* av = (const float*)d_in[9];
    const float* bv = (const float*)d_in[10];
    const float* wo = (const float*)d_in[11];
    const float* ao = (const float*)d_in[12];
    const float* bo = (const float*)d_in[13];
    const float* ln1 = (const float*)d_in[14];
    const float* wg = (const float*)d_in[15];
    const float* wu = (const float*)d_in[16];
    const float* wd = (const float*)d_in[17];
    const float* ln2 = (const float*)d_in[18];
    const float* norm_f = (const float*)d_in[19];

    float* gs = nullptr;
    cudaGetSymbolAddress((void**)&gs, g_scratch);

    float* dWQKV = gs + OFF_WQKV;
    float* dWO = gs + OFF_WO;
    float* dWG = gs + OFF_WG;  float* dWU = gs + OFF_WU;  float* dWD = gs + OFF_WD;
    float* X   = gs + OFF_X;   float* Hb  = gs + OFF_H;
    float* Qb  = gs + OFF_Q;   float* Kb  = gs + OFF_K;   float* Vb = gs + OFF_V;
    float* Cb  = gs + OFF_C;   float* SC  = gs + OFF_S;
    float* Gb  = gs + OFF_G;
    float* Tq  = gs + OFF_T;
    float* Tk  = Tq + (size_t)Mq * Rq;
    float* Tv  = Tk + (size_t)Mq * Rq;
    float* To  = Tv + (size_t)Mq * Rq;
    float* Ct  = gs + OFF_RT;
    float* St  = Ct + (size_t)Sq * 64;

    cudaFuncSetAttribute(k_gemm_mma, cudaFuncAttributeMaxDynamicSharedMemorySize,
                         MMA_SMEM_BYTES);
    cudaFuncSetAttribute(k_scores_mma, cudaFuncAttributeMaxDynamicSharedMemorySize,
                         MMA_SMEM_BYTES);
    cudaFuncSetAttribute(k_ctx_mma, cudaFuncAttributeMaxDynamicSharedMemorySize,
                         CTX_SMEM_BYTES);

    k_ropetab<<<(Sq * 64 + 255) / 256, 256>>>(Ct, St);

    // single-launch dequant over all 10 weight regions
    {
        DQTab tab;
        int nbD = (int)(DD / 64);                 // 65536
        int nbOD = (int)(Lq * DD / 64);           // 131072
        int nbFD2 = (int)(Lq * FD / 64);          // 352256
        int cum = 0, si = 0;
        for (int l = 0; l < Lq; l++) {
            tab.src[si] = wq + (size_t)l * DD;
            tab.dst[si] = dWQKV + (size_t)l * 3 * DD;
            tab.cum[si] = cum; cum += nbD; si++;
            tab.src[si] = wk + (size_t)l * DD;
            tab.dst[si] = dWQKV + (size_t)l * 3 * DD + DD;
            tab.cum[si] = cum; cum += nbD; si++;
            tab.src[si] = wv + (size_t)l * DD;
            tab.dst[si] = dWQKV + (size_t)l * 3 * DD + 2 * DD;
            tab.cum[si] = cum; cum += nbD; si++;
        }
        tab.src[si] = wo; tab.dst[si] = dWO; tab.cum[si] = cum; cum += nbOD; si++;
        tab.src[si] = wg; tab.dst[si] = dWG; tab.cum[si] = cum; cum += nbFD2; si++;
        tab.src[si] = wu; tab.dst[si] = dWU; tab.cum[si] = cum; cum += nbFD2; si++;
        tab.src[si] = wd; tab.dst[si] = dWD; tab.cum[si] = cum; cum += nbFD2; si++;
        tab.cum[NSEG] = cum;
        int nwarp = (cum + 3) / 4;
        k_dequant_all<<<(nwarp + 7) / 8, 256>>>(tab);
    }

    dim3 gQKV(3 * Dq / 128, Mq / 128);
    dim3 gDD(Dq / 128, Mq / 128);
    dim3 gFD(Fq / 128, Mq / 128);
    dim3 gSC(Sq / 128, Sq / 128, Bq * Hq);
    dim3 gCX(1, Sq / 128, Bq * Hq);

    for (int l = 0; l < Lq; l++) {
        const float* aqL = aq + (size_t)l * Rq * Dq;
        const float* bqL = bq + (size_t)l * Dq * Rq;
        const float* akL = ak + (size_t)l * Rq * Dq;
        const float* bkL = bk + (size_t)l * Dq * Rq;
        const float* avL = av + (size_t)l * Rq * Dq;
        const float* bvL = bv + (size_t)l * Dq * Rq;
        const float* aoL = ao + (size_t)l * Rq * Dq;
        const float* boL = bo + (size_t)l * Dq * Rq;
        const float* WQKVl = dWQKV + (size_t)l * 3 * DD;
        const float* WOl = dWO + (size_t)l * DD;
        const float* WGl = dWG + (size_t)l * FD;
        const float* WUl = dWU + (size_t)l * FD;
        const float* WDl = dWD + (size_t)l * FD;

        // layer 0 reads residual stream straight from inputs (no copy kernel)
        const float* Xin = (l == 0) ? inputs : X;

        k_rmsnorm_lora<<<Mq, 256>>>(Xin, ln1 + (size_t)l * Dq, aqL, akL, avL,
                                    Hb, Tq, Tk, Tv);

        k_gemm_mma<<<gQKV, 256, MMA_SMEM_BYTES>>>(Hb, WQKVl, Tq, bqL, bkL, bvL,
                                                  nullptr, nullptr, Qb, Dq, Dq, 1, 0, 0, 1);

        k_rope<<<(Mq * Hq * 64 + 255) / 256, 256>>>(Qb, Kb, Ct, St);

        k_scores_mma<<<gSC, 256, MMA_SMEM_BYTES>>>(Qb, Kb, amask, SC);
        k_softmax<<<Bq * Hq * Sq, 256>>>(SC);
        k_ctx_mma<<<gCX, 256, CTX_SMEM_BYTES>>>(SC, Vb, Cb);

        k_lora_t<<<Mq, 256>>>(Cb, aoL, To);
        // O-proj + residual: reads resid from Xin, writes X (layer0: inputs -> X)
        k_gemm_mma<<<gDD, 256, MMA_SMEM_BYTES>>>(Cb, WOl, To, boL, nullptr, nullptr,
                                                 nullptr, Xin, X, Dq, Dq, 1, 1, 0, 0);

        k_rmsnorm<<<Mq, 256>>>(X, ln2 + (size_t)l * Dq, Hb, 1);
        k_gemm_mma<<<gFD, 256, MMA_SMEM_BYTES>>>(Hb, WGl, nullptr, nullptr, nullptr, nullptr,
                                                 nullptr, nullptr, Gb, Fq, Dq, 0, 0, 0, 0);
        k_gemm_mma<<<gFD, 256, MMA_SMEM_BYTES>>>(Hb, WUl, nullptr, nullptr, nullptr, nullptr,
                                                 Gb, nullptr, Gb, Fq, Dq, 0, 0, 1, 0);
        k_gemm_mma<<<gDD, 256, MMA_SMEM_BYTES>>>(Gb, WDl, nullptr, nullptr, nullptr, nullptr,
                                                 nullptr, X, X, Dq, Fq, 0, 1, 0, 0);
    }

    k_rmsnorm<<<Mq, 256>>>(X, norm_f, (float*)d_out, 0);
}